// round 16
// baseline (speedup 1.0000x reference)
#include <cuda_runtime.h>

// BakeAugment — FINAL (session-best configuration; converged at the mixed-R/W
// HBM roofline).
//
// Math: at quality=15, every quantized DCT coefficient rounds to zero
// (|dctp/q| <= 8.0/33.33 < 0.5 with ~0.26 margin), so apply_jpeg() is the
// constant image (0, 0.34414*0.5 + 0.71414*0.5, 0) and `dither` is dead.
// The reference collapses to two elementwise streams:
//   inp    = clip( clip(Cc + gauss*0.03, 0,1) + sh_c, 1e-8,1)^0.9  (clip 0..1)
//   target = clip( clip(x + sh_c,          1e-8,1)^0.9, 0,1)
// with sh_c = shift[c]*0.05, Cc = (0, 0.52914, 0).
//
// Perf journal: powf -> MUFU fast path removed the compute wall (62 -> 35us).
// Remaining time is compulsory memory traffic: 200MB/replay (100MB unique
// reads of x+gauss, 100MB output writes) at ~5.7 TB/s achieved mixed R/W
// bandwidth = ~35.1us floor. Measured invariant (34.9-35.6us) across MLP
// 2/4/8, 128/256-bit accesses, all L2 evict/wt hints, split vs interleaved
// streams, TPB 256/512, and multi-wave vs persistent single-wave (persistent
// regressed to 37.4us). L2-persistence carve-outs and write elision are
// rule-barred. This config is the measured session best: 34.9us.

__device__ __forceinline__ float gamma_clip(float v) {
    v = fminf(fmaxf(v, 1e-8f), 1.0f);
    v = exp2f(0.9f * __log2f(v));       // MUFU.LG2 / FMUL / MUFU.EX2
    return fminf(v, 1.0f);              // >= 0 by construction
}

#define V   2    // float4 quads per stream per thread
#define TPB 256

__global__ void __launch_bounds__(TPB)
bake_kernel(const float4* __restrict__ x,
            const float4* __restrict__ gauss,
            const float* __restrict__ shift,
            float4* __restrict__ out,
            int n4)  // float4 elements per output tensor
{
    // Block owns a contiguous chunk of V*TPB quads; every memory instruction is
    // warp-contiguous (lane L accesses chunk + i*TPB + L).
    int chunk = blockIdx.x * (V * TPB);
    int q0    = chunk + threadIdx.x;

    // 65536 quads per channel image; chunk size (512) divides it, so the whole
    // chunk lies in one channel.
    int c = (chunk >> 16) % 3;
    float cc = (c == 1) ? (0.34414f * 0.5f + 0.71414f * 0.5f) : 0.0f;
    float sh = __ldg(&shift[c]) * 0.05f;

    // Front-batch all 2*V independent loads (MLP = 4), streaming hints.
    float4 g4[V], x4[V];
#pragma unroll
    for (int i = 0; i < V; i++) g4[i] = __ldcs(&gauss[q0 + i * TPB]);
#pragma unroll
    for (int i = 0; i < V; i++) x4[i] = __ldcs(&x[q0 + i * TPB]);

#pragma unroll
    for (int i = 0; i < V; i++) {
        float4 o;
        o.x = gamma_clip(fminf(fmaxf(fmaf(g4[i].x, 0.03f, cc), 0.0f), 1.0f) + sh);
        o.y = gamma_clip(fminf(fmaxf(fmaf(g4[i].y, 0.03f, cc), 0.0f), 1.0f) + sh);
        o.z = gamma_clip(fminf(fmaxf(fmaf(g4[i].z, 0.03f, cc), 0.0f), 1.0f) + sh);
        o.w = gamma_clip(fminf(fmaxf(fmaf(g4[i].w, 0.03f, cc), 0.0f), 1.0f) + sh);
        __stcs(&out[q0 + i * TPB], o);
    }

#pragma unroll
    for (int i = 0; i < V; i++) {
        float4 o;
        o.x = gamma_clip(x4[i].x + sh);
        o.y = gamma_clip(x4[i].y + sh);
        o.z = gamma_clip(x4[i].z + sh);
        o.w = gamma_clip(x4[i].w + sh);
        __stcs(&out[n4 + q0 + i * TPB], o);
    }
}

extern "C" void kernel_launch(void* const* d_in, const int* in_sizes, int n_in,
                              void* d_out, int out_size) {
    // Inputs per setup_inputs() order: x, dither, gauss, shift
    const float4* x     = (const float4*)d_in[0];
    // d_in[1] (dither) is mathematically unused: the JPEG stage is constant.
    const float4* gauss = (const float4*)d_in[2];
    const float*  shift = (const float*)d_in[3];
    float4* out = (float4*)d_out;

    int n  = out_size / 2;     // elements per output tensor (inp, target)
    int n4 = n / 4;            // 3,145,728 quads; divisible by V*TPB = 512
    int blocks = n4 / (V * TPB);
    bake_kernel<<<blocks, TPB>>>(x, gauss, shift, out, n4);
}

// round 17
// speedup vs baseline: 1.0045x; 1.0045x over previous
#include <cuda_runtime.h>

// BakeAugment — FINAL (session-best configuration; converged at the mixed-R/W
// HBM roofline).
//
// Math: at quality=15, every quantized DCT coefficient rounds to zero
// (|dctp/q| <= 8.0/33.33 < 0.5 with ~0.26 margin), so apply_jpeg() is the
// constant image (0, 0.34414*0.5 + 0.71414*0.5, 0) and `dither` is dead.
// The reference collapses to two elementwise streams:
//   inp    = clip( clip(Cc + gauss*0.03, 0,1) + sh_c, 1e-8,1)^0.9  (clip 0..1)
//   target = clip( clip(x + sh_c,          1e-8,1)^0.9, 0,1)
// with sh_c = shift[c]*0.05, Cc = (0, 0.52914, 0).
//
// Perf journal (16 rounds): powf -> MUFU fast path removed the compute wall
// (62 -> 35us). Remaining time is compulsory memory traffic: 200MB/replay
// (100MB unique reads of x+gauss, 100MB output writes) at ~5.7 TB/s achieved
// mixed R/W bandwidth = ~35.1us floor. Measured invariant (34.9-35.6us)
// across MLP 2/4/8, 128/256-bit accesses, all L2 evict/wt hints, split vs
// interleaved streams, TPB 256/512, and multi-wave vs persistent single-wave
// (persistent regressed to 37.4us). L2-persistence carve-outs and write
// elision are rule-barred. Session best with this config: 34.9us.

__device__ __forceinline__ float gamma_clip(float v) {
    v = fminf(fmaxf(v, 1e-8f), 1.0f);
    v = exp2f(0.9f * __log2f(v));       // MUFU.LG2 / FMUL / MUFU.EX2
    return fminf(v, 1.0f);              // >= 0 by construction
}

#define V   2    // float4 quads per stream per thread
#define TPB 256

__global__ void __launch_bounds__(TPB)
bake_kernel(const float4* __restrict__ x,
            const float4* __restrict__ gauss,
            const float* __restrict__ shift,
            float4* __restrict__ out,
            int n4)  // float4 elements per output tensor
{
    // Block owns a contiguous chunk of V*TPB quads; every memory instruction is
    // warp-contiguous (lane L accesses chunk + i*TPB + L).
    int chunk = blockIdx.x * (V * TPB);
    int q0    = chunk + threadIdx.x;

    // 65536 quads per channel image; chunk size (512) divides it, so the whole
    // chunk lies in one channel.
    int c = (chunk >> 16) % 3;
    float cc = (c == 1) ? (0.34414f * 0.5f + 0.71414f * 0.5f) : 0.0f;
    float sh = __ldg(&shift[c]) * 0.05f;

    // Front-batch all 2*V independent loads (MLP = 4), streaming hints.
    float4 g4[V], x4[V];
#pragma unroll
    for (int i = 0; i < V; i++) g4[i] = __ldcs(&gauss[q0 + i * TPB]);
#pragma unroll
    for (int i = 0; i < V; i++) x4[i] = __ldcs(&x[q0 + i * TPB]);

#pragma unroll
    for (int i = 0; i < V; i++) {
        float4 o;
        o.x = gamma_clip(fminf(fmaxf(fmaf(g4[i].x, 0.03f, cc), 0.0f), 1.0f) + sh);
        o.y = gamma_clip(fminf(fmaxf(fmaf(g4[i].y, 0.03f, cc), 0.0f), 1.0f) + sh);
        o.z = gamma_clip(fminf(fmaxf(fmaf(g4[i].z, 0.03f, cc), 0.0f), 1.0f) + sh);
        o.w = gamma_clip(fminf(fmaxf(fmaf(g4[i].w, 0.03f, cc), 0.0f), 1.0f) + sh);
        __stcs(&out[q0 + i * TPB], o);
    }

#pragma unroll
    for (int i = 0; i < V; i++) {
        float4 o;
        o.x = gamma_clip(x4[i].x + sh);
        o.y = gamma_clip(x4[i].y + sh);
        o.z = gamma_clip(x4[i].z + sh);
        o.w = gamma_clip(x4[i].w + sh);
        __stcs(&out[n4 + q0 + i * TPB], o);
    }
}

extern "C" void kernel_launch(void* const* d_in, const int* in_sizes, int n_in,
                              void* d_out, int out_size) {
    // Inputs per setup_inputs() order: x, dither, gauss, shift
    const float4* x     = (const float4*)d_in[0];
    // d_in[1] (dither) is mathematically unused: the JPEG stage is constant.
    const float4* gauss = (const float4*)d_in[2];
    const float*  shift = (const float*)d_in[3];
    float4* out = (float4*)d_out;

    int n  = out_size / 2;     // elements per output tensor (inp, target)
    int n4 = n / 4;            // 3,145,728 quads; divisible by V*TPB = 512
    int blocks = n4 / (V * TPB);
    bake_kernel<<<blocks, TPB>>>(x, gauss, shift, out, n4);
}